// round 6
// baseline (speedup 1.0000x reference)
#include <cuda_runtime.h>
#include <cuda_bf16.h>
#include <cstdint>

// Problem constants
#define BATCH 8
#define M_    4096   // H*W
#define C_    256    // feature dim
#define NPOOL 256
#define NTILE 32                      // M_/128
#define NTRI  (NTILE * (NTILE + 1) / 2)   // 528 lower-triangle tiles

// Scratch (device globals: allocation-free rule)
__device__ float    g_corr[(size_t)BATCH * M_ * M_];            // 512 MB
__device__ uint32_t g_h[(size_t)BATCH * M_ * C_ / 2];           // bf16 hi, 16 MB
__device__ uint32_t g_l[(size_t)BATCH * M_ * C_ / 2];           // bf16 lo, 16 MB

// ---------------------------------------------------------------------------
// Kernel 0: fp32 -> (H, L) bf16 split, plain row-major [b][m][c]
// ---------------------------------------------------------------------------
__global__ __launch_bounds__(256) void convert_kernel(const float* __restrict__ x) {
    const int idx = blockIdx.x * 256 + threadIdx.x;
    float2 v = ((const float2*)x)[idx];

    __nv_bfloat16 h0 = __float2bfloat16(v.x);
    __nv_bfloat16 h1 = __float2bfloat16(v.y);
    __nv_bfloat16 l0 = __float2bfloat16(v.x - __bfloat162float(h0));
    __nv_bfloat16 l1 = __float2bfloat16(v.y - __bfloat162float(h1));

    g_h[idx] = (uint32_t)__bfloat16_as_ushort(h0) | ((uint32_t)__bfloat16_as_ushort(h1) << 16);
    g_l[idx] = (uint32_t)__bfloat16_as_ushort(l0) | ((uint32_t)__bfloat16_as_ushort(l1) << 16);
}

// ---------------------------------------------------------------------------
// PTX helpers
// ---------------------------------------------------------------------------
__device__ __forceinline__ uint32_t smem_u32(const void* p) {
    uint32_t a;
    asm("{ .reg .u64 t; cvta.to.shared.u64 t, %1; cvt.u32.u64 %0, t; }" : "=r"(a) : "l"(p));
    return a;
}
__device__ __forceinline__ void ldsm_x4(uint32_t& r0, uint32_t& r1, uint32_t& r2, uint32_t& r3,
                                        uint32_t addr) {
    asm volatile("ldmatrix.sync.aligned.m8n8.x4.shared.b16 {%0,%1,%2,%3}, [%4];"
                 : "=r"(r0), "=r"(r1), "=r"(r2), "=r"(r3) : "r"(addr));
}
__device__ __forceinline__ void mma_bf16(float* d, const uint32_t* a, const uint32_t* b) {
    asm volatile("mma.sync.aligned.m16n8k16.row.col.f32.bf16.bf16.f32 "
                 "{%0,%1,%2,%3}, {%4,%5,%6,%7}, {%8,%9}, {%0,%1,%2,%3};"
                 : "+f"(d[0]), "+f"(d[1]), "+f"(d[2]), "+f"(d[3])
                 : "r"(a[0]), "r"(a[1]), "r"(a[2]), "r"(a[3]), "r"(b[0]), "r"(b[1]));
}
#define CP_ASYNC16(dst, src) \
    asm volatile("cp.async.cg.shared.global [%0], [%1], 16;" :: "r"(dst), "l"(src) : "memory")
#define CP_COMMIT() asm volatile("cp.async.commit_group;" ::: "memory")
#define CP_WAIT0()  asm volatile("cp.async.wait_group 0;" ::: "memory")
#define CP_WAIT1()  asm volatile("cp.async.wait_group 1;" ::: "memory")

// Swizzle for 32B rows (K-step 16): 2x16B chunks, chunk ^= (row>>2)&1.
// 8-row ldmatrix phases and 16B fill stores are bank-conflict-free.
__device__ __forceinline__ uint32_t swz16(uint32_t row, uint32_t chunk) {
    return row * 32u + ((chunk ^ (row >> 2)) & 1u) * 16u;
}

// ---------------------------------------------------------------------------
// Kernel 1: bf16-split GEMM, lower-triangle tiles only, cp.async 2-stage.
//   128x128 CTA tile, 8 warps of 64x32, K-step 16, 3 split products.
// ---------------------------------------------------------------------------
#define TILE_SM16 (128 * 32)      // 4096 B per operand tile
#define STG_P     33

union SmemU {
    unsigned char ops[2][4 * TILE_SM16];   // 2 stages x (Ah, Al, Bh, Bl) = 32 KB
    float stage[128 * STG_P];
};

__global__ __launch_bounds__(256) void gemm_mma_kernel() {
    __shared__ __align__(16) SmemU smu;

    const int t    = threadIdx.x;
    const int wid  = t >> 5;
    const int lane = t & 31;
    const int b    = blockIdx.z;

    // decode linear triangular index -> (ti >= tj)
    int ti = (int)((sqrtf(8.0f * blockIdx.x + 1.0f) - 1.0f) * 0.5f);
    while ((ti + 1) * (ti + 2) / 2 <= (int)blockIdx.x) ti++;
    while (ti * (ti + 1) / 2 > (int)blockIdx.x) ti--;
    const int tj = blockIdx.x - ti * (ti + 1) / 2;

    const uint32_t sbase = smem_u32(smu.ops);
    const uint32_t O_AH = 0, O_AL = TILE_SM16, O_BH = 2 * TILE_SM16, O_BL = 3 * TILE_SM16;

    const unsigned char* gh = (const unsigned char*)g_h;
    const unsigned char* gl = (const unsigned char*)g_l;
    const size_t rowA = (size_t)(b * M_ + ti * 128);
    const size_t rowB = (size_t)(b * M_ + tj * 128);

    // per-thread fill slot: 256 chunks of 16B per tile
    const int fr = t >> 1;            // row 0..127
    const int fc = t & 1;             // 16B chunk
    const uint32_t so = swz16((uint32_t)fr, (uint32_t)fc);
    const size_t gAr = (rowA + fr) * (C_ * 2) + fc * 16;
    const size_t gBr = (rowB + fr) * (C_ * 2) + fc * 16;

    const int mw = (wid & 1) * 64;
    const int nw = (wid >> 1) * 32;

    float acc[4][4][4];
#pragma unroll
    for (int i = 0; i < 4; i++)
#pragma unroll
        for (int j = 0; j < 4; j++)
#pragma unroll
            for (int c = 0; c < 4; c++) acc[i][j][c] = 0.0f;

    // issue loads for K-step ks into buffer buf
    auto issue = [&](int ks, int buf) {
        const uint32_t sb = sbase + (uint32_t)buf * (4 * TILE_SM16);
        const size_t kb = (size_t)ks * 32;   // 16 bf16 = 32 bytes
        CP_ASYNC16(sb + O_AH + so, gh + gAr + kb);
        CP_ASYNC16(sb + O_AL + so, gl + gAr + kb);
        CP_ASYNC16(sb + O_BH + so, gh + gBr + kb);
        CP_ASYNC16(sb + O_BL + so, gl + gBr + kb);
    };

    issue(0, 0);
    CP_COMMIT();

    for (int ks = 0; ks < 16; ks++) {
        if (ks < 15) { issue(ks + 1, (ks + 1) & 1); CP_COMMIT(); CP_WAIT1(); }
        else         { CP_WAIT0(); }
        __syncthreads();

        const uint32_t sb = sbase + (uint32_t)(ks & 1) * (4 * TILE_SM16);
#pragma unroll
        for (int p = 0; p < 3; p++) {
            const uint32_t sA = sb + (p == 2 ? O_AL : O_AH);
            const uint32_t sB = sb + (p == 1 ? O_BL : O_BH);
            uint32_t a[4][4];
#pragma unroll
            for (int i = 0; i < 4; i++) {
                const uint32_t arow = (uint32_t)(mw + i * 16 + (lane & 15));
                const uint32_t achk = (uint32_t)((lane >> 4) & 1);
                ldsm_x4(a[i][0], a[i][1], a[i][2], a[i][3], sA + swz16(arow, achk));
            }
            uint32_t bf[4][2];
#pragma unroll
            for (int jb = 0; jb < 2; jb++) {
                const uint32_t brow = (uint32_t)(nw + jb * 16 + (lane & 7) +
                                                 ((lane >> 4) & 1) * 8);
                const uint32_t bchk = (uint32_t)((lane >> 3) & 1);
                uint32_t r0, r1, r2, r3;
                ldsm_x4(r0, r1, r2, r3, sB + swz16(brow, bchk));
                bf[jb * 2 + 0][0] = r0; bf[jb * 2 + 0][1] = r1;
                bf[jb * 2 + 1][0] = r2; bf[jb * 2 + 1][1] = r3;
            }
#pragma unroll
            for (int i = 0; i < 4; i++)
#pragma unroll
                for (int j = 0; j < 4; j++)
                    mma_bf16(acc[i][j], a[i], bf[j]);
        }
        __syncthreads();
    }

    // ---- scale once ----
    const float scale = 1.0f / 256.0f;
#pragma unroll
    for (int i = 0; i < 4; i++)
#pragma unroll
        for (int j = 0; j < 4; j++)
#pragma unroll
            for (int c = 0; c < 4; c++) acc[i][j][c] *= scale;

    const int g4 = lane >> 2;
    const int t4 = lane & 3;
    float* Cb = g_corr + (size_t)b * M_ * M_;

    // ---- direct store at (ti, tj) ----
    const int colb = tj * 128 + nw + t4 * 2;
#pragma unroll
    for (int i = 0; i < 4; i++) {
        const int row0 = ti * 128 + mw + i * 16 + g4;
#pragma unroll
        for (int j = 0; j < 4; j++) {
            float2 v0 = make_float2(acc[i][j][0], acc[i][j][1]);
            float2 v1 = make_float2(acc[i][j][2], acc[i][j][3]);
            *(float2*)(Cb + (size_t)row0 * M_ + colb + j * 8)       = v0;
            *(float2*)(Cb + (size_t)(row0 + 8) * M_ + colb + j * 8) = v1;
        }
    }

    // ---- transposed store at (tj, ti), off-diagonal only ----
    if (ti != tj) {
        for (int ch = 0; ch < 4; ch++) {
            __syncthreads();
            if ((wid >> 1) == ch) {
#pragma unroll
                for (int i = 0; i < 4; i++) {
                    const int r0 = mw + i * 16 + g4;
#pragma unroll
                    for (int j = 0; j < 4; j++) {
                        const int cl = t4 * 2 + j * 8;
                        smu.stage[r0 * STG_P + cl]           = acc[i][j][0];
                        smu.stage[r0 * STG_P + cl + 1]       = acc[i][j][1];
                        smu.stage[(r0 + 8) * STG_P + cl]     = acc[i][j][2];
                        smu.stage[(r0 + 8) * STG_P + cl + 1] = acc[i][j][3];
                    }
                }
            }
            __syncthreads();
#pragma unroll
            for (int s = 0; s < 4; s++) {
                const int cc = wid + s * 8;
                float* dst = Cb + (size_t)(tj * 128 + ch * 32 + cc) * M_ + ti * 128;
#pragma unroll
                for (int k = 0; k < 4; k++)
                    dst[lane + 32 * k] = smu.stage[(lane + 32 * k) * STG_P + cc];
            }
        }
    }
}

// ---------------------------------------------------------------------------
// Kernel 2: exact percentile selection via 2048-bin histogram (no full sort).
// One CTA per row; 256 threads x 16 values in registers.
// ---------------------------------------------------------------------------
#define NBIN 2048

__global__ __launch_bounds__(256) void select_kernel(float* __restrict__ out) {
    __shared__ uint32_t hist[NBIN];          // counts, then per-bucket fill
    __shared__ uint32_t pref[NBIN + 1];      // ascending exclusive prefix
    __shared__ uint32_t cbase[NBIN];         // candidate base offsets
    __shared__ uint32_t needmask[NBIN / 32];
    __shared__ uint32_t cand[M_];            // candidate keys (<= 4096 always)
    __shared__ uint32_t sred[256];
    __shared__ float    fred[16];
    __shared__ float    s_vmin, s_vmax;

    const int t = threadIdx.x;
    const int row = blockIdx.x;
    const float* __restrict__ src = g_corr + (size_t)row * M_;

    float v[16];
#pragma unroll
    for (int i = 0; i < 4; i++) {
        float4 w = ((const float4*)src)[i * 256 + t];
        v[i * 4 + 0] = w.x; v[i * 4 + 1] = w.y;
        v[i * 4 + 2] = w.z; v[i * 4 + 3] = w.w;
    }

    // zero hist + flags
#pragma unroll
    for (int i = 0; i < NBIN / 256; i++) hist[t + 256 * i] = 0;
    if (t < NBIN / 32) needmask[t] = 0;

    // block min/max
    float lmin = v[0], lmax = v[0];
#pragma unroll
    for (int i = 1; i < 16; i++) { lmin = fminf(lmin, v[i]); lmax = fmaxf(lmax, v[i]); }
#pragma unroll
    for (int o = 16; o > 0; o >>= 1) {
        lmin = fminf(lmin, __shfl_xor_sync(0xFFFFFFFFu, lmin, o));
        lmax = fmaxf(lmax, __shfl_xor_sync(0xFFFFFFFFu, lmax, o));
    }
    if ((t & 31) == 0) { fred[t >> 5] = lmin; fred[8 + (t >> 5)] = lmax; }
    __syncthreads();
    if (t == 0) {
        float a = fred[0], bb = fred[8];
        for (int i = 1; i < 8; i++) { a = fminf(a, fred[i]); bb = fmaxf(bb, fred[8 + i]); }
        s_vmin = a; s_vmax = bb;
    }
    __syncthreads();
    const float vmin = s_vmin, vmax = s_vmax;

    if (!(vmax > vmin)) {   // degenerate: all values equal
        out[(size_t)row * NPOOL + t] = vmin;
        return;
    }

    // histogram + order keys
    const float bscale = (float)NBIN / (vmax - vmin);
    int bin[16]; uint32_t key[16];
#pragma unroll
    for (int i = 0; i < 16; i++) {
        int bb = (int)((v[i] - vmin) * bscale);
        bin[i] = bb > NBIN - 1 ? NBIN - 1 : (bb < 0 ? 0 : bb);
        uint32_t u = __float_as_uint(v[i]);
        key[i] = u ^ ((u >> 31) ? 0xFFFFFFFFu : 0x80000000u);
        atomicAdd(&hist[bin[i]], 1u);
    }
    __syncthreads();

    // exclusive prefix over hist (8 bins/thread + block scan)
    {
        uint32_t loc[8], s = 0;
#pragma unroll
        for (int j = 0; j < 8; j++) { loc[j] = s; s += hist[t * 8 + j]; }
        sred[t] = s; __syncthreads();
        for (int o = 1; o < 256; o <<= 1) {
            uint32_t x = (t >= o) ? sred[t - o] : 0; __syncthreads();
            sred[t] += x; __syncthreads();
        }
        uint32_t base = sred[t] - s;
#pragma unroll
        for (int j = 0; j < 8; j++) pref[t * 8 + j] = base + loc[j];
        if (t == 0) pref[NBIN] = M_;
    }
    __syncthreads();

    // rank -> bucket (ascending index a = 4095 - descending rank)
    const float step = 4094.0f / 255.0f;
    int q = (int)rintf(fmaf((float)t, step, 1.0f));
    if (q < 1) q = 1; if (q > M_ - 1) q = M_ - 1;
    const uint32_t a = (uint32_t)(M_ - 1 - q);
    int lo = 0, hi = NBIN - 1;
    while (lo < hi) {
        int mid = (lo + hi + 1) >> 1;
        if (pref[mid] <= a) lo = mid; else hi = mid - 1;
    }
    const int myb = lo;
    const uint32_t la = a - pref[myb];
    atomicOr(&needmask[myb >> 5], 1u << (myb & 31));
    __syncthreads();

    // cbase = exclusive scan over flagged bucket counts; reset fill counters
    {
        uint32_t loc[8], s = 0;
#pragma unroll
        for (int j = 0; j < 8; j++) {
            int bb = t * 8 + j;
            uint32_t c = ((needmask[bb >> 5] >> (bb & 31)) & 1u) ? (pref[bb + 1] - pref[bb]) : 0u;
            loc[j] = s; s += c;
            hist[bb] = 0;
        }
        sred[t] = s; __syncthreads();
        for (int o = 1; o < 256; o <<= 1) {
            uint32_t x = (t >= o) ? sred[t - o] : 0; __syncthreads();
            sred[t] += x; __syncthreads();
        }
        uint32_t base = sred[t] - s;
#pragma unroll
        for (int j = 0; j < 8; j++) cbase[t * 8 + j] = base + loc[j];
    }
    __syncthreads();

    // scatter candidates of flagged buckets
#pragma unroll
    for (int i = 0; i < 16; i++) {
        int bb = bin[i];
        if ((needmask[bb >> 5] >> (bb & 31)) & 1u) {
            uint32_t pos = cbase[bb] + atomicAdd(&hist[bb], 1u);
            cand[pos] = key[i];
        }
    }
    __syncthreads();

    // exact la-th smallest within my bucket (ties are equal values)
    const uint32_t n = pref[myb + 1] - pref[myb];
    const uint32_t base = cbase[myb];
    uint32_t myval = cand[base];
    for (uint32_t i = 0; i < n; i++) {
        uint32_t ki = cand[base + i];
        uint32_t r = 0;
        for (uint32_t j = 0; j < n; j++) {
            uint32_t kj = cand[base + j];
            r += (kj < ki) || (kj == ki && j < i);
        }
        if (r == la) { myval = ki; break; }
    }
    uint32_t ub = (myval & 0x80000000u) ? (myval ^ 0x80000000u) : ~myval;
    out[(size_t)row * NPOOL + t] = __uint_as_float(ub);
}

// ---------------------------------------------------------------------------
// Launch
// ---------------------------------------------------------------------------
extern "C" void kernel_launch(void* const* d_in, const int* in_sizes, int n_in,
                              void* d_out, int out_size) {
    (void)in_sizes; (void)n_in; (void)out_size;
    const float* x = (const float*)d_in[0];
    float* out = (float*)d_out;

    convert_kernel<<<(BATCH * M_ * C_ / 2) / 256, 256>>>(x);

    dim3 ggrid(NTRI, 1, BATCH);
    gemm_mma_kernel<<<ggrid, 256>>>();

    select_kernel<<<BATCH * M_, 256>>>(out);
}

// round 9
// speedup vs baseline: 1.2675x; 1.2675x over previous
#include <cuda_runtime.h>
#include <cuda_bf16.h>
#include <cstdint>

// Problem constants
#define BATCH 8
#define M_    4096   // H*W
#define C_    256    // feature dim
#define NPOOL 256
#define NTILE 32                      // M_/128
#define NTRI  (NTILE * (NTILE + 1) / 2)   // 528 lower-triangle tiles

// Scratch (device globals: allocation-free rule)
__device__ float    g_corr[(size_t)BATCH * M_ * M_];            // 512 MB
__device__ uint32_t g_h[(size_t)BATCH * M_ * C_ / 2];           // bf16 hi, 16 MB
__device__ uint32_t g_l[(size_t)BATCH * M_ * C_ / 2];           // bf16 lo, 16 MB

// ---------------------------------------------------------------------------
// Kernel 0: fp32 -> (H, L) bf16 split, plain row-major [b][m][c]
// ---------------------------------------------------------------------------
__global__ __launch_bounds__(256) void convert_kernel(const float* __restrict__ x) {
    const int idx = blockIdx.x * 256 + threadIdx.x;
    float2 v = ((const float2*)x)[idx];

    __nv_bfloat16 h0 = __float2bfloat16(v.x);
    __nv_bfloat16 h1 = __float2bfloat16(v.y);
    __nv_bfloat16 l0 = __float2bfloat16(v.x - __bfloat162float(h0));
    __nv_bfloat16 l1 = __float2bfloat16(v.y - __bfloat162float(h1));

    g_h[idx] = (uint32_t)__bfloat16_as_ushort(h0) | ((uint32_t)__bfloat16_as_ushort(h1) << 16);
    g_l[idx] = (uint32_t)__bfloat16_as_ushort(l0) | ((uint32_t)__bfloat16_as_ushort(l1) << 16);
}

// ---------------------------------------------------------------------------
// mma.sync helpers
// ---------------------------------------------------------------------------
__device__ __forceinline__ uint32_t smem_u32(const void* p) {
    uint32_t a;
    asm("{ .reg .u64 t; cvta.to.shared.u64 t, %1; cvt.u32.u64 %0, t; }" : "=r"(a) : "l"(p));
    return a;
}
__device__ __forceinline__ void ldsm_x4(uint32_t& r0, uint32_t& r1, uint32_t& r2, uint32_t& r3,
                                        uint32_t addr) {
    asm volatile("ldmatrix.sync.aligned.m8n8.x4.shared.b16 {%0,%1,%2,%3}, [%4];"
                 : "=r"(r0), "=r"(r1), "=r"(r2), "=r"(r3) : "r"(addr));
}
__device__ __forceinline__ void mma_bf16(float* d, const uint32_t* a, const uint32_t* b) {
    asm volatile("mma.sync.aligned.m16n8k16.row.col.f32.bf16.bf16.f32 "
                 "{%0,%1,%2,%3}, {%4,%5,%6,%7}, {%8,%9}, {%0,%1,%2,%3};"
                 : "+f"(d[0]), "+f"(d[1]), "+f"(d[2]), "+f"(d[3])
                 : "r"(a[0]), "r"(a[1]), "r"(a[2]), "r"(a[3]), "r"(b[0]), "r"(b[1]));
}

// XOR-swizzled smem offset: 64B rows of 4x16B chunks, chunk ^= (row>>1)&3.
__device__ __forceinline__ uint32_t swz(uint32_t row, uint32_t chunk) {
    return row * 64u + ((chunk ^ (row >> 1)) & 3u) * 16u;
}

// ---------------------------------------------------------------------------
// Kernel 1: bf16-split GEMM, lower-triangle tiles (round-5 known-good version)
//   128x128 CTA tile, 8 warps of 64x32, K-step 32, 3 split products.
// ---------------------------------------------------------------------------
#define TILE_SM (128 * 64)        // 8192 B per operand tile
#define STG_P   33                // transpose stage pitch (floats)

union SmemU {
    unsigned char ops[4 * TILE_SM];        // Ah, Al, Bh, Bl (32 KB)
    float stage[128 * STG_P];              // 16.9 KB transpose stage
};

__global__ __launch_bounds__(256) void gemm_mma_kernel() {
    __shared__ __align__(16) SmemU smu;
    unsigned char* sm = smu.ops;

    const int t    = threadIdx.x;
    const int wid  = t >> 5;
    const int lane = t & 31;
    const int b    = blockIdx.z;

    // decode linear triangular index -> (ti >= tj)
    int ti = (int)((sqrtf(8.0f * blockIdx.x + 1.0f) - 1.0f) * 0.5f);
    while ((ti + 1) * (ti + 2) / 2 <= (int)blockIdx.x) ti++;
    while (ti * (ti + 1) / 2 > (int)blockIdx.x) ti--;
    const int tj = blockIdx.x - ti * (ti + 1) / 2;

    const uint32_t sbase = smem_u32(sm);
    const uint32_t OFF_AH = 0, OFF_AL = TILE_SM, OFF_BH = 2 * TILE_SM, OFF_BL = 3 * TILE_SM;

    const unsigned char* gh = (const unsigned char*)g_h;
    const unsigned char* gl = (const unsigned char*)g_l;
    const size_t rowA = (size_t)(b * M_ + ti * 128);
    const size_t rowB = (size_t)(b * M_ + tj * 128);

    const int mw = (wid & 1) * 64;
    const int nw = (wid >> 1) * 32;

    float acc[4][4][4];
#pragma unroll
    for (int i = 0; i < 4; i++)
#pragma unroll
        for (int j = 0; j < 4; j++)
#pragma unroll
            for (int c = 0; c < 4; c++) acc[i][j][c] = 0.0f;

    for (int k0 = 0; k0 < C_; k0 += 32) {
#pragma unroll
        for (int j = 0; j < 2; j++) {
            const int q = j * 256 + t;
            const int r = q >> 2;
            const int c = q & 3;
            const size_t gbyteA = (rowA + r) * (C_ * 2) + (size_t)(k0 + c * 8) * 2;
            const size_t gbyteB = (rowB + r) * (C_ * 2) + (size_t)(k0 + c * 8) * 2;
            const uint32_t so = swz((uint32_t)r, (uint32_t)c);
            *(float4*)(sm + OFF_AH + so) = *(const float4*)(gh + gbyteA);
            *(float4*)(sm + OFF_AL + so) = *(const float4*)(gl + gbyteA);
            *(float4*)(sm + OFF_BH + so) = *(const float4*)(gh + gbyteB);
            *(float4*)(sm + OFF_BL + so) = *(const float4*)(gl + gbyteB);
        }
        __syncthreads();

#pragma unroll
        for (int p = 0; p < 3; p++) {
            const uint32_t sA = sbase + (p == 2 ? OFF_AL : OFF_AH);
            const uint32_t sB = sbase + (p == 1 ? OFF_BL : OFF_BH);
#pragma unroll
            for (int k16 = 0; k16 < 2; k16++) {
                uint32_t a[4][4];
#pragma unroll
                for (int i = 0; i < 4; i++) {
                    const uint32_t arow = (uint32_t)(mw + i * 16 + (lane & 15));
                    const uint32_t achk = (uint32_t)(k16 * 2 + ((lane >> 4) & 1));
                    ldsm_x4(a[i][0], a[i][1], a[i][2], a[i][3], sA + swz(arow, achk));
                }
                uint32_t bf[4][2];
#pragma unroll
                for (int jb = 0; jb < 2; jb++) {
                    const uint32_t brow = (uint32_t)(nw + jb * 16 + (lane & 7) +
                                                     ((lane >> 4) & 1) * 8);
                    const uint32_t bchk = (uint32_t)(k16 * 2 + ((lane >> 3) & 1));
                    uint32_t r0, r1, r2, r3;
                    ldsm_x4(r0, r1, r2, r3, sB + swz(brow, bchk));
                    bf[jb * 2 + 0][0] = r0; bf[jb * 2 + 0][1] = r1;
                    bf[jb * 2 + 1][0] = r2; bf[jb * 2 + 1][1] = r3;
                }
#pragma unroll
                for (int i = 0; i < 4; i++)
#pragma unroll
                    for (int j = 0; j < 4; j++)
                        mma_bf16(acc[i][j], a[i], bf[j]);
            }
        }
        __syncthreads();
    }

    // ---- scale once ----
    const float scale = 1.0f / 256.0f;
#pragma unroll
    for (int i = 0; i < 4; i++)
#pragma unroll
        for (int j = 0; j < 4; j++)
#pragma unroll
            for (int c = 0; c < 4; c++) acc[i][j][c] *= scale;

    const int g4 = lane >> 2;
    const int t4 = lane & 3;
    float* Cb = g_corr + (size_t)b * M_ * M_;

    // ---- direct store at (ti, tj) ----
    const int colb = tj * 128 + nw + t4 * 2;
#pragma unroll
    for (int i = 0; i < 4; i++) {
        const int row0 = ti * 128 + mw + i * 16 + g4;
#pragma unroll
        for (int j = 0; j < 4; j++) {
            float2 v0 = make_float2(acc[i][j][0], acc[i][j][1]);
            float2 v1 = make_float2(acc[i][j][2], acc[i][j][3]);
            *(float2*)(Cb + (size_t)row0 * M_ + colb + j * 8)       = v0;
            *(float2*)(Cb + (size_t)(row0 + 8) * M_ + colb + j * 8) = v1;
        }
    }

    // ---- transposed store at (tj, ti), off-diagonal only ----
    if (ti != tj) {
        for (int ch = 0; ch < 4; ch++) {
            __syncthreads();
            if ((wid >> 1) == ch) {
#pragma unroll
                for (int i = 0; i < 4; i++) {
                    const int r0 = mw + i * 16 + g4;
#pragma unroll
                    for (int j = 0; j < 4; j++) {
                        const int cl = t4 * 2 + j * 8;
                        smu.stage[r0 * STG_P + cl]           = acc[i][j][0];
                        smu.stage[r0 * STG_P + cl + 1]       = acc[i][j][1];
                        smu.stage[(r0 + 8) * STG_P + cl]     = acc[i][j][2];
                        smu.stage[(r0 + 8) * STG_P + cl + 1] = acc[i][j][3];
                    }
                }
            }
            __syncthreads();
#pragma unroll
            for (int s = 0; s < 4; s++) {
                const int cc = wid + s * 8;
                float* dst = Cb + (size_t)(tj * 128 + ch * 32 + cc) * M_ + ti * 128;
#pragma unroll
                for (int k = 0; k < 4; k++)
                    dst[lane + 32 * k] = smu.stage[(lane + 32 * k) * STG_P + cc];
            }
        }
    }
}

// ---------------------------------------------------------------------------
// Kernel 2: exact percentile selection, v2.
//   4096 bins; counting-sort-by-bucket via cursor scatter; shuffle block scan.
//   One CTA per row; 256 threads x 16 values in registers.
// ---------------------------------------------------------------------------
#define NBIN 4096

__global__ __launch_bounds__(256) void select_kernel(float* __restrict__ out) {
    __shared__ uint32_t pref[NBIN + 1];   // counts -> exclusive prefix -> cursors
    __shared__ uint32_t cand[M_];         // bucket-grouped order keys
    __shared__ uint32_t wsum[8];
    __shared__ float    fred[16];
    __shared__ float    s_vmin, s_vmax;

    const int t = threadIdx.x;
    const int row = blockIdx.x;
    const float* __restrict__ src = g_corr + (size_t)row * M_;

    float v[16];
#pragma unroll
    for (int i = 0; i < 4; i++) {
        float4 w = ((const float4*)src)[i * 256 + t];
        v[i * 4 + 0] = w.x; v[i * 4 + 1] = w.y;
        v[i * 4 + 2] = w.z; v[i * 4 + 3] = w.w;
    }

    // zero counts
#pragma unroll
    for (int i = 0; i < NBIN / 256; i++) pref[t + 256 * i] = 0;

    // block min/max
    float lmin = v[0], lmax = v[0];
#pragma unroll
    for (int i = 1; i < 16; i++) { lmin = fminf(lmin, v[i]); lmax = fmaxf(lmax, v[i]); }
#pragma unroll
    for (int o = 16; o > 0; o >>= 1) {
        lmin = fminf(lmin, __shfl_xor_sync(0xFFFFFFFFu, lmin, o));
        lmax = fmaxf(lmax, __shfl_xor_sync(0xFFFFFFFFu, lmax, o));
    }
    if ((t & 31) == 0) { fred[t >> 5] = lmin; fred[8 + (t >> 5)] = lmax; }
    __syncthreads();
    if (t == 0) {
        float a = fred[0], bb = fred[8];
        for (int i = 1; i < 8; i++) { a = fminf(a, fred[i]); bb = fmaxf(bb, fred[8 + i]); }
        s_vmin = a; s_vmax = bb;
    }
    __syncthreads();
    const float vmin = s_vmin, vmax = s_vmax;

    if (!(vmax > vmin)) {                 // degenerate: all equal (uniform branch)
        out[(size_t)row * NPOOL + t] = vmin;
        return;
    }

    // histogram + monotone order keys
    const float bscale = (float)NBIN / (vmax - vmin);
    int bin[16]; uint32_t key[16];
#pragma unroll
    for (int i = 0; i < 16; i++) {
        int bb = (int)((v[i] - vmin) * bscale);
        bin[i] = bb > NBIN - 1 ? NBIN - 1 : (bb < 0 ? 0 : bb);
        uint32_t u = __float_as_uint(v[i]);
        key[i] = u ^ ((u >> 31) ? 0xFFFFFFFFu : 0x80000000u);
        atomicAdd(&pref[bin[i]], 1u);
    }
    __syncthreads();

    // in-place exclusive prefix: 16 bins/thread + warp shuffle + 8-warp combine
    {
        uint32_t cnt[16], s = 0;
#pragma unroll
        for (int j = 0; j < 16; j++) cnt[j] = pref[t * 16 + j];
#pragma unroll
        for (int j = 0; j < 16; j++) { uint32_t x = cnt[j]; cnt[j] = s; s += x; }
        uint32_t tot = s, wex = 0;
#pragma unroll
        for (int o = 1; o < 32; o <<= 1) {
            uint32_t x = __shfl_up_sync(0xFFFFFFFFu, s, o);
            if ((t & 31) >= o) s += x;
        }
        wex = s - tot;                                   // warp-exclusive
        if ((t & 31) == 31) wsum[t >> 5] = s;            // warp total
        __syncthreads();
        uint32_t base = 0;
        for (int w = 0; w < (t >> 5); w++) base += wsum[w];
#pragma unroll
        for (int j = 0; j < 16; j++) pref[t * 16 + j] = base + wex + cnt[j];
        if (t == 0) pref[NBIN] = M_;
    }
    __syncthreads();

    // rank -> bucket; capture base/n/la BEFORE scatter mutates pref
    const float step = 4094.0f / 255.0f;
    int q = (int)rintf(fmaf((float)t, step, 1.0f));
    if (q < 1) q = 1; if (q > M_ - 1) q = M_ - 1;
    const uint32_t a = (uint32_t)(M_ - 1 - q);           // ascending index
    int lo = 0, hi = NBIN - 1;
    while (lo < hi) {
        int mid = (lo + hi + 1) >> 1;
        if (pref[mid] <= a) lo = mid; else hi = mid - 1;
    }
    const uint32_t mybase = pref[lo];
    const uint32_t n  = pref[lo + 1] - mybase;
    const uint32_t la = a - mybase;
    __syncthreads();                                     // searches done before scatter

    // cursor scatter: full counting sort by bucket (pref becomes cursors)
#pragma unroll
    for (int i = 0; i < 16; i++) {
        uint32_t pos = atomicAdd(&pref[bin[i]], 1u);
        cand[pos] = key[i];
    }
    __syncthreads();

    // exact la-th smallest among cand[mybase .. mybase+n)
    uint32_t myval = cand[mybase];
    for (uint32_t i = 0; i < n; i++) {
        uint32_t ki = cand[mybase + i];
        uint32_t r = 0;
        for (uint32_t j = 0; j < n; j++) {
            uint32_t kj = cand[mybase + j];
            r += (kj < ki) || (kj == ki && j < i);
        }
        if (r == la) { myval = ki; break; }
    }
    uint32_t ub = (myval & 0x80000000u) ? (myval ^ 0x80000000u) : ~myval;
    out[(size_t)row * NPOOL + t] = __uint_as_float(ub);
}

// ---------------------------------------------------------------------------
// Launch
// ---------------------------------------------------------------------------
extern "C" void kernel_launch(void* const* d_in, const int* in_sizes, int n_in,
                              void* d_out, int out_size) {
    (void)in_sizes; (void)n_in; (void)out_size;
    const float* x = (const float*)d_in[0];
    float* out = (float*)d_out;

    convert_kernel<<<(BATCH * M_ * C_ / 2) / 256, 256>>>(x);

    dim3 ggrid(NTRI, 1, BATCH);
    gemm_mma_kernel<<<ggrid, 256>>>();

    select_kernel<<<BATCH * M_, 256>>>(out);
}

// round 10
// speedup vs baseline: 1.3619x; 1.0744x over previous
#include <cuda_runtime.h>
#include <cuda_bf16.h>
#include <cstdint>

// Problem constants
#define BATCH 8
#define M_    4096   // H*W
#define C_    256    // feature dim
#define NPOOL 256
#define NTILE 32                      // M_/128
#define NTRI  (NTILE * (NTILE + 1) / 2)   // 528 lower-triangle tiles

// Scratch (device globals: allocation-free rule)
__device__ float    g_corr[(size_t)BATCH * M_ * M_];            // 512 MB
__device__ uint32_t g_h[(size_t)BATCH * M_ * C_ / 2];           // bf16 hi, 16 MB
__device__ uint32_t g_l[(size_t)BATCH * M_ * C_ / 2];           // bf16 lo, 16 MB

// ---------------------------------------------------------------------------
// Kernel 0: fp32 -> (H, L) bf16 split, plain row-major [b][m][c]
// ---------------------------------------------------------------------------
__global__ __launch_bounds__(256) void convert_kernel(const float* __restrict__ x) {
    const int idx = blockIdx.x * 256 + threadIdx.x;
    float2 v = ((const float2*)x)[idx];

    __nv_bfloat16 h0 = __float2bfloat16(v.x);
    __nv_bfloat16 h1 = __float2bfloat16(v.y);
    __nv_bfloat16 l0 = __float2bfloat16(v.x - __bfloat162float(h0));
    __nv_bfloat16 l1 = __float2bfloat16(v.y - __bfloat162float(h1));

    g_h[idx] = (uint32_t)__bfloat16_as_ushort(h0) | ((uint32_t)__bfloat16_as_ushort(h1) << 16);
    g_l[idx] = (uint32_t)__bfloat16_as_ushort(l0) | ((uint32_t)__bfloat16_as_ushort(l1) << 16);
}

// ---------------------------------------------------------------------------
// mma.sync helpers
// ---------------------------------------------------------------------------
__device__ __forceinline__ uint32_t smem_u32(const void* p) {
    uint32_t a;
    asm("{ .reg .u64 t; cvta.to.shared.u64 t, %1; cvt.u32.u64 %0, t; }" : "=r"(a) : "l"(p));
    return a;
}
__device__ __forceinline__ void ldsm_x4(uint32_t& r0, uint32_t& r1, uint32_t& r2, uint32_t& r3,
                                        uint32_t addr) {
    asm volatile("ldmatrix.sync.aligned.m8n8.x4.shared.b16 {%0,%1,%2,%3}, [%4];"
                 : "=r"(r0), "=r"(r1), "=r"(r2), "=r"(r3) : "r"(addr));
}
__device__ __forceinline__ void mma_bf16(float* d, const uint32_t* a, const uint32_t* b) {
    asm volatile("mma.sync.aligned.m16n8k16.row.col.f32.bf16.bf16.f32 "
                 "{%0,%1,%2,%3}, {%4,%5,%6,%7}, {%8,%9}, {%0,%1,%2,%3};"
                 : "+f"(d[0]), "+f"(d[1]), "+f"(d[2]), "+f"(d[3])
                 : "r"(a[0]), "r"(a[1]), "r"(a[2]), "r"(a[3]), "r"(b[0]), "r"(b[1]));
}

// XOR-swizzled smem offset: 64B rows of 4x16B chunks, chunk ^= (row>>1)&3.
__device__ __forceinline__ uint32_t swz(uint32_t row, uint32_t chunk) {
    return row * 64u + ((chunk ^ (row >> 1)) & 3u) * 16u;
}

// ---------------------------------------------------------------------------
// Kernel 1: bf16-split GEMM, lower-triangle tiles. 128x128 CTA tile,
//   8 warps of 64x32, K-step 32, 3 split products (HH, HL, LH).
//   B-fragments hoisted across products: 12 ldsm per k16 instead of 18.
// ---------------------------------------------------------------------------
#define TILE_SM (128 * 64)        // 8192 B per operand tile
#define STG_P   33                // transpose stage pitch (floats)

union SmemU {
    unsigned char ops[4 * TILE_SM];        // Ah, Al, Bh, Bl (32 KB)
    float stage[128 * STG_P];              // 16.9 KB transpose stage
};

__global__ __launch_bounds__(256) void gemm_mma_kernel() {
    __shared__ __align__(16) SmemU smu;
    unsigned char* sm = smu.ops;

    const int t    = threadIdx.x;
    const int wid  = t >> 5;
    const int lane = t & 31;
    const int b    = blockIdx.z;

    // decode linear triangular index -> (ti >= tj)
    int ti = (int)((sqrtf(8.0f * blockIdx.x + 1.0f) - 1.0f) * 0.5f);
    while ((ti + 1) * (ti + 2) / 2 <= (int)blockIdx.x) ti++;
    while (ti * (ti + 1) / 2 > (int)blockIdx.x) ti--;
    const int tj = blockIdx.x - ti * (ti + 1) / 2;

    const uint32_t sbase = smem_u32(sm);
    const uint32_t OFF_AH = 0, OFF_AL = TILE_SM, OFF_BH = 2 * TILE_SM, OFF_BL = 3 * TILE_SM;

    const unsigned char* gh = (const unsigned char*)g_h;
    const unsigned char* gl = (const unsigned char*)g_l;
    const size_t rowA = (size_t)(b * M_ + ti * 128);
    const size_t rowB = (size_t)(b * M_ + tj * 128);

    const int mw = (wid & 1) * 64;
    const int nw = (wid >> 1) * 32;

    float acc[4][4][4];
#pragma unroll
    for (int i = 0; i < 4; i++)
#pragma unroll
        for (int j = 0; j < 4; j++)
#pragma unroll
            for (int c = 0; c < 4; c++) acc[i][j][c] = 0.0f;

    for (int k0 = 0; k0 < C_; k0 += 32) {
#pragma unroll
        for (int j = 0; j < 2; j++) {
            const int q = j * 256 + t;
            const int r = q >> 2;
            const int c = q & 3;
            const size_t gbyteA = (rowA + r) * (C_ * 2) + (size_t)(k0 + c * 8) * 2;
            const size_t gbyteB = (rowB + r) * (C_ * 2) + (size_t)(k0 + c * 8) * 2;
            const uint32_t so = swz((uint32_t)r, (uint32_t)c);
            *(float4*)(sm + OFF_AH + so) = *(const float4*)(gh + gbyteA);
            *(float4*)(sm + OFF_AL + so) = *(const float4*)(gl + gbyteA);
            *(float4*)(sm + OFF_BH + so) = *(const float4*)(gh + gbyteB);
            *(float4*)(sm + OFF_BL + so) = *(const float4*)(gl + gbyteB);
        }
        __syncthreads();

#pragma unroll
        for (int k16 = 0; k16 < 2; k16++) {
            // ---- B fragments once per k16 (Bh and Bl) ----
            uint32_t bh[4][2], bl[4][2];
#pragma unroll
            for (int jb = 0; jb < 2; jb++) {
                const uint32_t brow = (uint32_t)(nw + jb * 16 + (lane & 7) +
                                                 ((lane >> 4) & 1) * 8);
                const uint32_t bchk = (uint32_t)(k16 * 2 + ((lane >> 3) & 1));
                uint32_t r0, r1, r2, r3;
                ldsm_x4(r0, r1, r2, r3, sbase + OFF_BH + swz(brow, bchk));
                bh[jb * 2 + 0][0] = r0; bh[jb * 2 + 0][1] = r1;
                bh[jb * 2 + 1][0] = r2; bh[jb * 2 + 1][1] = r3;
                ldsm_x4(r0, r1, r2, r3, sbase + OFF_BL + swz(brow, bchk));
                bl[jb * 2 + 0][0] = r0; bl[jb * 2 + 0][1] = r1;
                bl[jb * 2 + 1][0] = r2; bl[jb * 2 + 1][1] = r3;
            }
            uint32_t a[4][4];
            // ---- Ah: products Ah*Bh and Ah*Bl ----
#pragma unroll
            for (int i = 0; i < 4; i++) {
                const uint32_t arow = (uint32_t)(mw + i * 16 + (lane & 15));
                const uint32_t achk = (uint32_t)(k16 * 2 + ((lane >> 4) & 1));
                ldsm_x4(a[i][0], a[i][1], a[i][2], a[i][3], sbase + OFF_AH + swz(arow, achk));
            }
#pragma unroll
            for (int i = 0; i < 4; i++)
#pragma unroll
                for (int j = 0; j < 4; j++) {
                    mma_bf16(acc[i][j], a[i], bh[j]);
                    mma_bf16(acc[i][j], a[i], bl[j]);
                }
            // ---- Al: product Al*Bh ----
#pragma unroll
            for (int i = 0; i < 4; i++) {
                const uint32_t arow = (uint32_t)(mw + i * 16 + (lane & 15));
                const uint32_t achk = (uint32_t)(k16 * 2 + ((lane >> 4) & 1));
                ldsm_x4(a[i][0], a[i][1], a[i][2], a[i][3], sbase + OFF_AL + swz(arow, achk));
            }
#pragma unroll
            for (int i = 0; i < 4; i++)
#pragma unroll
                for (int j = 0; j < 4; j++)
                    mma_bf16(acc[i][j], a[i], bh[j]);
        }
        __syncthreads();
    }

    // ---- scale once ----
    const float scale = 1.0f / 256.0f;
#pragma unroll
    for (int i = 0; i < 4; i++)
#pragma unroll
        for (int j = 0; j < 4; j++)
#pragma unroll
            for (int c = 0; c < 4; c++) acc[i][j][c] *= scale;

    const int g4 = lane >> 2;
    const int t4 = lane & 3;
    float* Cb = g_corr + (size_t)b * M_ * M_;

    // ---- direct store at (ti, tj) ----
    const int colb = tj * 128 + nw + t4 * 2;
#pragma unroll
    for (int i = 0; i < 4; i++) {
        const int row0 = ti * 128 + mw + i * 16 + g4;
#pragma unroll
        for (int j = 0; j < 4; j++) {
            float2 v0 = make_float2(acc[i][j][0], acc[i][j][1]);
            float2 v1 = make_float2(acc[i][j][2], acc[i][j][3]);
            *(float2*)(Cb + (size_t)row0 * M_ + colb + j * 8)       = v0;
            *(float2*)(Cb + (size_t)(row0 + 8) * M_ + colb + j * 8) = v1;
        }
    }

    // ---- transposed store at (tj, ti), off-diagonal only ----
    if (ti != tj) {
        for (int ch = 0; ch < 4; ch++) {
            __syncthreads();
            if ((wid >> 1) == ch) {
#pragma unroll
                for (int i = 0; i < 4; i++) {
                    const int r0 = mw + i * 16 + g4;
#pragma unroll
                    for (int j = 0; j < 4; j++) {
                        const int cl = t4 * 2 + j * 8;
                        smu.stage[r0 * STG_P + cl]           = acc[i][j][0];
                        smu.stage[r0 * STG_P + cl + 1]       = acc[i][j][1];
                        smu.stage[(r0 + 8) * STG_P + cl]     = acc[i][j][2];
                        smu.stage[(r0 + 8) * STG_P + cl + 1] = acc[i][j][3];
                    }
                }
            }
            __syncthreads();
#pragma unroll
            for (int s = 0; s < 4; s++) {
                const int cc = wid + s * 8;
                float* dst = Cb + (size_t)(tj * 128 + ch * 32 + cc) * M_ + ti * 128;
#pragma unroll
                for (int k = 0; k < 4; k++)
                    dst[lane + 32 * k] = smu.stage[(lane + 32 * k) * STG_P + cc];
            }
        }
    }
}

// ---------------------------------------------------------------------------
// Kernel 2: exact percentile selection, v3.
//   Keys staged in smem (low regs), padded conflict-free scan, 2048 bins.
//   One CTA per row; 256 threads.
// ---------------------------------------------------------------------------
#define NBIN 2048
#define PADI(i) ((i) + ((i) >> 5))

__global__ __launch_bounds__(256) void select_kernel(float* __restrict__ out) {
    __shared__ uint32_t keys[M_];              // 16 KB, [j*256 + t]
    __shared__ uint32_t pref[PADI(NBIN) + 1];  // padded counts->prefix->cursors
    __shared__ uint32_t cand[M_];              // 16 KB bucket-grouped keys
    __shared__ uint32_t wsum[8];
    __shared__ float    fred[16];
    __shared__ float    s_vmin, s_vmax;

    const int t = threadIdx.x;
    const int row = blockIdx.x;
    const float* __restrict__ src = g_corr + (size_t)row * M_;

    float v[16];
#pragma unroll
    for (int i = 0; i < 4; i++) {
        float4 w = ((const float4*)src)[i * 256 + t];
        v[i * 4 + 0] = w.x; v[i * 4 + 1] = w.y;
        v[i * 4 + 2] = w.z; v[i * 4 + 3] = w.w;
    }

    // zero padded counts
    for (int i = t; i < PADI(NBIN) + 1; i += 256) pref[i] = 0;

    // block min/max
    float lmin = v[0], lmax = v[0];
#pragma unroll
    for (int i = 1; i < 16; i++) { lmin = fminf(lmin, v[i]); lmax = fmaxf(lmax, v[i]); }
#pragma unroll
    for (int o = 16; o > 0; o >>= 1) {
        lmin = fminf(lmin, __shfl_xor_sync(0xFFFFFFFFu, lmin, o));
        lmax = fmaxf(lmax, __shfl_xor_sync(0xFFFFFFFFu, lmax, o));
    }
    if ((t & 31) == 0) { fred[t >> 5] = lmin; fred[8 + (t >> 5)] = lmax; }
    __syncthreads();
    if (t == 0) {
        float a = fred[0], bb = fred[8];
        for (int i = 1; i < 8; i++) { a = fminf(a, fred[i]); bb = fmaxf(bb, fred[8 + i]); }
        s_vmin = a; s_vmax = bb;
    }
    __syncthreads();
    const float vmin = s_vmin, vmax = s_vmax;

    if (!(vmax > vmin)) {                 // degenerate: all equal (uniform branch)
        out[(size_t)row * NPOOL + t] = vmin;
        return;
    }

    // histogram (from regs) + stage monotone keys to smem (conflict-free)
    const float bscale = (float)NBIN / (vmax - vmin);
#pragma unroll
    for (int i = 0; i < 16; i++) {
        int bb = (int)((v[i] - vmin) * bscale);
        bb = bb > NBIN - 1 ? NBIN - 1 : (bb < 0 ? 0 : bb);
        uint32_t u = __float_as_uint(v[i]);
        keys[i * 256 + t] = u ^ ((u >> 31) ? 0xFFFFFFFFu : 0x80000000u);
        atomicAdd(&pref[PADI(bb)], 1u);
    }
    __syncthreads();

    // exclusive prefix: 8 bins/thread (padded, conflict-free) + shuffle scan
    {
        uint32_t cnt[8], s = 0;
#pragma unroll
        for (int j = 0; j < 8; j++) cnt[j] = pref[PADI(t * 8 + j)];
#pragma unroll
        for (int j = 0; j < 8; j++) { uint32_t x = cnt[j]; cnt[j] = s; s += x; }
        uint32_t tot = s;
#pragma unroll
        for (int o = 1; o < 32; o <<= 1) {
            uint32_t x = __shfl_up_sync(0xFFFFFFFFu, s, o);
            if ((t & 31) >= o) s += x;
        }
        uint32_t wex = s - tot;
        if ((t & 31) == 31) wsum[t >> 5] = s;
        __syncthreads();
        uint32_t base = 0;
        for (int w = 0; w < (t >> 5); w++) base += wsum[w];
#pragma unroll
        for (int j = 0; j < 8; j++) pref[PADI(t * 8 + j)] = base + wex + cnt[j];
        if (t == 0) pref[PADI(NBIN)] = M_;
    }
    __syncthreads();

    // rank -> bucket; capture base/n/la BEFORE scatter mutates pref
    const float step = 4094.0f / 255.0f;
    int q = (int)rintf(fmaf((float)t, step, 1.0f));
    if (q < 1) q = 1; if (q > M_ - 1) q = M_ - 1;
    const uint32_t a = (uint32_t)(M_ - 1 - q);           // ascending index
    int lo = 0, hi = NBIN - 1;
    while (lo < hi) {
        int mid = (lo + hi + 1) >> 1;
        if (pref[PADI(mid)] <= a) lo = mid; else hi = mid - 1;
    }
    const uint32_t mybase = pref[PADI(lo)];
    const uint32_t n  = pref[PADI(lo + 1)] - mybase;
    const uint32_t la = a - mybase;
    __syncthreads();                                     // searches done before scatter

    // cursor scatter: counting sort by bucket (pref becomes cursors)
#pragma unroll
    for (int i = 0; i < 16; i++) {
        const uint32_t k = keys[i * 256 + t];
        // reconstruct value bit-exactly, recompute bin with identical formula
        const uint32_t u = (k & 0x80000000u) ? (k ^ 0x80000000u) : ~k;
        const float val = __uint_as_float(u);
        int bb = (int)((val - vmin) * bscale);
        bb = bb > NBIN - 1 ? NBIN - 1 : (bb < 0 ? 0 : bb);
        uint32_t pos = atomicAdd(&pref[PADI(bb)], 1u);
        cand[pos] = k;
    }
    __syncthreads();

    // exact la-th smallest among cand[mybase .. mybase+n)
    uint32_t myval = cand[mybase];
    for (uint32_t i = 0; i < n; i++) {
        uint32_t ki = cand[mybase + i];
        uint32_t r = 0;
        for (uint32_t j = 0; j < n; j++) {
            uint32_t kj = cand[mybase + j];
            r += (kj < ki) || (kj == ki && j < i);
        }
        if (r == la) { myval = ki; break; }
    }
    uint32_t ub = (myval & 0x80000000u) ? (myval ^ 0x80000000u) : ~myval;
    out[(size_t)row * NPOOL + t] = __uint_as_float(ub);
}

// ---------------------------------------------------------------------------
// Launch
// ---------------------------------------------------------------------------
extern "C" void kernel_launch(void* const* d_in, const int* in_sizes, int n_in,
                              void* d_out, int out_size) {
    (void)in_sizes; (void)n_in; (void)out_size;
    const float* x = (const float*)d_in[0];
    float* out = (float*)d_out;

    convert_kernel<<<(BATCH * M_ * C_ / 2) / 256, 256>>>(x);

    dim3 ggrid(NTRI, 1, BATCH);
    gemm_mma_kernel<<<ggrid, 256>>>();

    select_kernel<<<BATCH * M_, 256>>>(out);
}